// round 15
// baseline (speedup 1.0000x reference)
#include <cuda_runtime.h>
#include <cuda_bf16.h>
#include <mma.h>
#include <cstdint>
#include <stdint.h>
#include <math.h>
#include <float.h>

using namespace nvcuda;

#define SLEN 2048
#define CDIM 1024
#define NH   16
#define HD   64
#define TOPK 128
#define C3   3072

// ---------------- scratch (static device globals; no allocs allowed) ----------
__device__ float g_qkv[SLEN * C3];                       // [s][3072]
__device__ float g_q[NH * SLEN * HD];
__device__ float g_k[NH * SLEN * HD];
__device__ float g_sc[(size_t)NH * SLEN * SLEN];
__device__ float g_ctx[SLEN * CDIM];
__device__ float g_cos[SLEN * 32];
__device__ float g_sin[SLEN * 32];
// bf16 hi/lo splits (value path)
__device__ __nv_bfloat16 g_xhi[SLEN * CDIM];
__device__ __nv_bfloat16 g_xlo[SLEN * CDIM];
__device__ __nv_bfloat16 g_wvhi[CDIM * CDIM];
__device__ __nv_bfloat16 g_wvlo[CDIM * CDIM];
__device__ __nv_bfloat16 g_wphi[CDIM * CDIM];
__device__ __nv_bfloat16 g_wplo[CDIM * CDIM];
__device__ __nv_bfloat16 g_chi[SLEN * CDIM];
__device__ __nv_bfloat16 g_clo[SLEN * CDIM];

// ---------------- RoPE trig tables (reference op-by-op fp32 rounding) ----------
__global__ void build_tables(float* __restrict__ ct, float* __restrict__ st)
{
    int t = blockIdx.x * blockDim.x + threadIdx.x;
    if (t >= SLEN * 32) return;
    int i = t & 31, s = t >> 5;
    double te = (double)(2 * i) / 64.0;
    float b = (float)pow(10000.0, te);
    float inv = __fdiv_rn(1.0f, b);
    float ang = __fmul_rn((float)s, inv);
    ct[t] = (float)cos((double)ang);
    st[t] = (float)sin((double)ang);
}

// ---------------- fp32 -> bf16 hi/lo split --------------------------------------
__global__ void split_bf16(const float* __restrict__ src,
                           __nv_bfloat16* __restrict__ hi,
                           __nv_bfloat16* __restrict__ lo, int n)
{
    int i = (blockIdx.x * 256 + threadIdx.x) * 4;
    if (i >= n) return;
    float4 v = *(const float4*)(src + i);
    float vv[4] = {v.x, v.y, v.z, v.w};
    __nv_bfloat16 h[4], l[4];
#pragma unroll
    for (int e = 0; e < 4; e++) {
        h[e] = __float2bfloat16(vv[e]);
        l[e] = __float2bfloat16(vv[e] - __bfloat162float(h[e]));
    }
    *(uint2*)(hi + i) = *(uint2*)h;
    *(uint2*)(lo + i) = *(uint2*)l;
}

// ---------------- fast NT SGEMM (bitwise-frozen ascending-k FMA chain) ---------
__global__ __launch_bounds__(256, 2) void sgemm_nt_fast(const float* __restrict__ A,
                                                        const float* __restrict__ B,
                                                        float* __restrict__ Cmat,
                                                        int N, int K, int ldc)
{
    __shared__ float As[2][16][128];
    __shared__ float Bs[2][16][128];
    const int tid = threadIdx.x;
    const int bm = blockIdx.y * 128;
    const int bn = blockIdx.x * 128;
    const int tx = tid & 15;
    const int ty = tid >> 4;
    const int lr = tid >> 1;
    const int lc = (tid & 1) * 8;

    const float* Ap = A + (size_t)(bm + lr) * K + lc;
    const float* Bp = B + (size_t)(bn + lr) * K + lc;

    float acc[8][8] = {};
    float4 pa0 = *(const float4*)Ap;
    float4 pa1 = *(const float4*)(Ap + 4);
    float4 pb0 = *(const float4*)Bp;
    float4 pb1 = *(const float4*)(Bp + 4);
    int buf = 0;
    As[0][lc + 0][lr] = pa0.x; As[0][lc + 1][lr] = pa0.y;
    As[0][lc + 2][lr] = pa0.z; As[0][lc + 3][lr] = pa0.w;
    As[0][lc + 4][lr] = pa1.x; As[0][lc + 5][lr] = pa1.y;
    As[0][lc + 6][lr] = pa1.z; As[0][lc + 7][lr] = pa1.w;
    Bs[0][lc + 0][lr] = pb0.x; Bs[0][lc + 1][lr] = pb0.y;
    Bs[0][lc + 2][lr] = pb0.z; Bs[0][lc + 3][lr] = pb0.w;
    Bs[0][lc + 4][lr] = pb1.x; Bs[0][lc + 5][lr] = pb1.y;
    Bs[0][lc + 6][lr] = pb1.z; Bs[0][lc + 7][lr] = pb1.w;
    __syncthreads();

    const int ntiles = K >> 4;
    for (int kt = 0; kt < ntiles; kt++) {
        const bool more = (kt + 1 < ntiles);
        if (more) {
            const float* An = Ap + (size_t)(kt + 1) * 16;
            const float* Bn = Bp + (size_t)(kt + 1) * 16;
            pa0 = *(const float4*)An; pa1 = *(const float4*)(An + 4);
            pb0 = *(const float4*)Bn; pb1 = *(const float4*)(Bn + 4);
        }
#pragma unroll
        for (int k = 0; k < 16; k++) {
            float4 a0 = *(const float4*)&As[buf][k][ty * 8];
            float4 a1 = *(const float4*)&As[buf][k][ty * 8 + 4];
            float4 b0 = *(const float4*)&Bs[buf][k][tx * 8];
            float4 b1 = *(const float4*)&Bs[buf][k][tx * 8 + 4];
            float av[8] = {a0.x, a0.y, a0.z, a0.w, a1.x, a1.y, a1.z, a1.w};
            float bv[8] = {b0.x, b0.y, b0.z, b0.w, b1.x, b1.y, b1.z, b1.w};
#pragma unroll
            for (int i = 0; i < 8; i++)
#pragma unroll
                for (int j = 0; j < 8; j++)
                    acc[i][j] = __fmaf_rn(av[i], bv[j], acc[i][j]);
        }
        if (more) {
            buf ^= 1;
            As[buf][lc + 0][lr] = pa0.x; As[buf][lc + 1][lr] = pa0.y;
            As[buf][lc + 2][lr] = pa0.z; As[buf][lc + 3][lr] = pa0.w;
            As[buf][lc + 4][lr] = pa1.x; As[buf][lc + 5][lr] = pa1.y;
            As[buf][lc + 6][lr] = pa1.z; As[buf][lc + 7][lr] = pa1.w;
            Bs[buf][lc + 0][lr] = pb0.x; Bs[buf][lc + 1][lr] = pb0.y;
            Bs[buf][lc + 2][lr] = pb0.z; Bs[buf][lc + 3][lr] = pb0.w;
            Bs[buf][lc + 4][lr] = pb1.x; Bs[buf][lc + 5][lr] = pb1.y;
            Bs[buf][lc + 6][lr] = pb1.z; Bs[buf][lc + 7][lr] = pb1.w;
            __syncthreads();
        }
    }
    (void)N;
#pragma unroll
    for (int i = 0; i < 8; i++) {
        float* Cp = Cmat + (size_t)(bm + ty * 8 + i) * ldc + bn + tx * 8;
        *(float4*)Cp       = make_float4(acc[i][0], acc[i][1], acc[i][2], acc[i][3]);
        *(float4*)(Cp + 4) = make_float4(acc[i][4], acc[i][5], acc[i][6], acc[i][7]);
    }
}

// ================= wmma bf16x3 GEMM (value path; classic HMMA) ==================
__global__ __launch_bounds__(128) void gemm_wmma_bf16x3(
    const __nv_bfloat16* __restrict__ Ahi, const __nv_bfloat16* __restrict__ Alo,
    const __nv_bfloat16* __restrict__ Bhi, const __nv_bfloat16* __restrict__ Blo,
    float* __restrict__ Cmat, int ldc, int K)
{
    __shared__ __nv_bfloat16 sAhi[64][72];
    __shared__ __nv_bfloat16 sAlo[64][72];
    __shared__ __nv_bfloat16 sBhi[64][72];
    __shared__ __nv_bfloat16 sBlo[64][72];

    const int tid = threadIdx.x;
    const int wid = tid >> 5;
    const int bm = blockIdx.y * 64;
    const int bn = blockIdx.x * 64;
    const int wm = (wid >> 1) * 32;
    const int wn = (wid & 1) * 32;

    wmma::fragment<wmma::accumulator, 16, 16, 16, float> acc[2][2];
#pragma unroll
    for (int i = 0; i < 2; i++)
#pragma unroll
        for (int j = 0; j < 2; j++)
            wmma::fill_fragment(acc[i][j], 0.0f);

    const int nchunks = K >> 6;
    for (int kc = 0; kc < nchunks; kc++) {
        const int kofs = kc * 64;
#pragma unroll
        for (int i = 0; i < 4; i++) {
            int id = tid + i * 128;
            int row = id >> 3, col = (id & 7) * 8;
            *(uint4*)&sAhi[row][col] = *(const uint4*)(Ahi + (size_t)(bm + row) * K + kofs + col);
            *(uint4*)&sAlo[row][col] = *(const uint4*)(Alo + (size_t)(bm + row) * K + kofs + col);
            *(uint4*)&sBhi[row][col] = *(const uint4*)(Bhi + (size_t)(bn + row) * K + kofs + col);
            *(uint4*)&sBlo[row][col] = *(const uint4*)(Blo + (size_t)(bn + row) * K + kofs + col);
        }
        __syncthreads();

#pragma unroll
        for (int kk = 0; kk < 4; kk++) {
            wmma::fragment<wmma::matrix_a, 16, 16, 16, __nv_bfloat16, wmma::row_major> ahi[2], alo[2];
            wmma::fragment<wmma::matrix_b, 16, 16, 16, __nv_bfloat16, wmma::col_major> bhi[2], blo[2];
#pragma unroll
            for (int i = 0; i < 2; i++) {
                wmma::load_matrix_sync(ahi[i], &sAhi[wm + 16 * i][kk * 16], 72);
                wmma::load_matrix_sync(alo[i], &sAlo[wm + 16 * i][kk * 16], 72);
            }
#pragma unroll
            for (int j = 0; j < 2; j++) {
                wmma::load_matrix_sync(bhi[j], &sBhi[wn + 16 * j][kk * 16], 72);
                wmma::load_matrix_sync(blo[j], &sBlo[wn + 16 * j][kk * 16], 72);
            }
#pragma unroll
            for (int i = 0; i < 2; i++)
#pragma unroll
                for (int j = 0; j < 2; j++) {
                    wmma::mma_sync(acc[i][j], ahi[i], bhi[j], acc[i][j]);
                    wmma::mma_sync(acc[i][j], ahi[i], blo[j], acc[i][j]);
                    wmma::mma_sync(acc[i][j], alo[i], bhi[j], acc[i][j]);
                }
        }
        __syncthreads();
    }

#pragma unroll
    for (int i = 0; i < 2; i++)
#pragma unroll
        for (int j = 0; j < 2; j++)
            wmma::store_matrix_sync(Cmat + (size_t)(bm + wm + 16 * i) * ldc + bn + wn + 16 * j,
                                    acc[i][j], ldc, wmma::mem_row_major);
}

// ---------------- RoPE + L2 normalize (bitwise-frozen) -------------------------
__global__ void rope_norm_kernel(const float* __restrict__ qkv,
                                 const float* __restrict__ ct,
                                 const float* __restrict__ st,
                                 float* __restrict__ gq, float* __restrict__ gk)
{
    __shared__ float buf[8][64];
    __shared__ float nrm[8];
    const int w = threadIdx.x >> 5;
    const int gw = (blockIdx.x * blockDim.x + threadIdx.x) >> 5;
    const int lane = threadIdx.x & 31;
    if (gw >= 2 * NH * SLEN) return;
    const int which = (gw >= NH * SLEN) ? 1 : 0;
    const int rem = which ? gw - NH * SLEN : gw;
    const int h = rem >> 11;
    const int s = rem & (SLEN - 1);

    const float* src = qkv + (size_t)s * C3 + which * CDIM + h * HD;
    float x0 = src[2 * lane];
    float x1 = src[2 * lane + 1];

    float cv = ct[s * 32 + lane];
    float sv = st[s * 32 + lane];

    float r0 = __fadd_rn(__fmul_rn(x0, cv), __fmul_rn(-x1, sv));
    float r1 = __fadd_rn(__fmul_rn(x1, cv), __fmul_rn(x0, sv));

    buf[w][2 * lane]     = r0;
    buf[w][2 * lane + 1] = r1;
    __syncwarp();
    if (lane == 0) {
        float l0 = 0.f, l1 = 0.f, l2 = 0.f, l3 = 0.f;
        for (int t = 0; t < 16; t++) {
            float v0 = buf[w][4 * t + 0];
            float v1 = buf[w][4 * t + 1];
            float v2 = buf[w][4 * t + 2];
            float v3 = buf[w][4 * t + 3];
            l0 = __fadd_rn(l0, __fmul_rn(v0, v0));
            l1 = __fadd_rn(l1, __fmul_rn(v1, v1));
            l2 = __fadd_rn(l2, __fmul_rn(v2, v2));
            l3 = __fadd_rn(l3, __fmul_rn(v3, v3));
        }
        float ssum = __fadd_rn(__fadd_rn(l0, l1), __fadd_rn(l2, l3));
        nrm[w] = fmaxf(__fsqrt_rn(ssum), 1e-12f);
    }
    __syncwarp();
    const float nv = nrm[w];

    float* dst = (which ? gk : gq) + ((size_t)h * SLEN + s) * HD;
    dst[2 * lane]     = __fdiv_rn(r0, nv);
    dst[2 * lane + 1] = __fdiv_rn(r1, nv);
}

// ---------------- causal scores, ONE head (bitwise-frozen chain) ---------------
__global__ __launch_bounds__(256) void scores_kernel_h(const float* __restrict__ gq,
                                                       const float* __restrict__ gk,
                                                       float* __restrict__ gs,
                                                       int h)
{
    const int jb = blockIdx.x * 128;
    const int qb = blockIdx.y * 128;
    if (jb > qb) return;

    extern __shared__ float smemf[];
    float (*Qs)[129] = (float(*)[129])smemf;
    float (*Ks)[129] = (float(*)[129])(smemf + 64 * 129);

    const int tid = threadIdx.x;
    const float* qp = gq + ((size_t)h * SLEN + qb) * HD;
    const float* kp = gk + ((size_t)h * SLEN + jb) * HD;
#pragma unroll
    for (int i = 0; i < 32; i++) {
        int idx = tid + i * 256;
        int r = idx >> 6, c = idx & 63;
        Qs[c][r] = qp[idx];
        Ks[c][r] = kp[idx];
    }
    __syncthreads();

    const int tx = tid & 15, ty = tid >> 4;
    float acc[8][8] = {};
#pragma unroll
    for (int k = 0; k < 64; k++) {
        float a[8], b[8];
#pragma unroll
        for (int i = 0; i < 8; i++) a[i] = Qs[k][ty + 16 * i];
#pragma unroll
        for (int j = 0; j < 8; j++) b[j] = Ks[k][tx + 16 * j];
#pragma unroll
        for (int i = 0; i < 8; i++)
#pragma unroll
            for (int j = 0; j < 8; j++)
                acc[i][j] = __fmaf_rn(a[i], b[j], acc[i][j]);
    }
#pragma unroll
    for (int i = 0; i < 8; i++) {
        float* outp = gs + ((size_t)h * SLEN + qb + ty + 16 * i) * SLEN + jb + tx;
#pragma unroll
        for (int j = 0; j < 8; j++)
            outp[16 * j] = __fmul_rn(acc[i][j], 0.125f);
    }
}

// ---------------- helpers ------------------------------------------------------
__device__ __forceinline__ unsigned f2key(float f)
{
    unsigned u = __float_as_uint(f);
    return (u & 0x80000000u) ? ~u : (u | 0x80000000u);
}

// ---------------- hard top-k, ONE head ----------------------------------------
__global__ __launch_bounds__(256) void topk_av_kernel_h(const float* __restrict__ gs,
                                                        const float* __restrict__ qkv,
                                                        float* __restrict__ ctx,
                                                        int h)
{
    __shared__ float sc[SLEN];
    __shared__ int   clist[SLEN];
    __shared__ float fred[8];
    __shared__ int   ired[8];
    __shared__ int   hist[256];
    __shared__ int   ss[257];
    __shared__ float s_max;
    __shared__ float s_z;
    __shared__ unsigned s_prefix;
    __shared__ int   s_want;
    __shared__ int   s_cnt;
    __shared__ int   s_tcnt;
    __shared__ int   s_bcnt;
    __shared__ int   tlist[64];
    __shared__ int   sidx[256];
    __shared__ float sw[256];
    __shared__ float yacc[4][64];

    const int q = (SLEN - 1) - blockIdx.x;   // long rows first
    const int n = q + 1;
    const int tid = threadIdx.x;
    const int lane = tid & 31, wid = tid >> 5;
    const bool doSel = (n > TOPK);

    const float* src = gs + ((size_t)h * SLEN + q) * SLEN;

    hist[tid] = 0;
    if (tid == 0) { s_cnt = 0; s_tcnt = 0; s_bcnt = 0; }
    __syncthreads();

    float m = -FLT_MAX;
    const int nIter = (n + 1023) >> 10;
    for (int it = 0; it < nIter; it++) {
        int j0 = it * 1024 + tid * 4;
        float4 v = make_float4(0.f, 0.f, 0.f, 0.f);
        if (j0 + 3 < n) {
            v = *(const float4*)(src + j0);
        } else if (j0 < n) {
            v.x = src[j0];
            if (j0 + 1 < n) v.y = src[j0 + 1];
            if (j0 + 2 < n) v.z = src[j0 + 2];
            if (j0 + 3 < n) v.w = src[j0 + 3];
        }
        if (j0 < n) {
            sc[j0] = v.x;
            if (j0 + 1 < n) sc[j0 + 1] = v.y;
            if (j0 + 2 < n) sc[j0 + 2] = v.z;
            if (j0 + 3 < n) sc[j0 + 3] = v.w;
        }
        float vv[4] = {v.x, v.y, v.z, v.w};
#pragma unroll
        for (int e = 0; e < 4; e++) {
            bool ok = (j0 + e) < n;
            if (ok) m = fmaxf(m, vv[e]);
            if (doSel) {
                int b = ok ? (int)(f2key(vv[e]) >> 24) : -1;
                unsigned same = __match_any_sync(0xffffffffu, b);
                if (b >= 0 && lane == (__ffs(same) - 1)) atomicAdd(&hist[b], __popc(same));
            }
        }
    }
#pragma unroll
    for (int o = 16; o; o >>= 1) m = fmaxf(m, __shfl_xor_sync(0xffffffffu, m, o));
    if (lane == 0) fred[wid] = m;
    __syncthreads();
    if (tid == 0) {
        float mm = fred[0];
        for (int w = 1; w < 8; w++) mm = fmaxf(mm, fred[w]);
        s_max = mm;
    }
    __syncthreads();
    m = s_max;

    const int nPad = (n + 255) & ~255;
    unsigned T = 0;
    int r = 0;

    if (doSel) {
        {
            int v = hist[tid];
#pragma unroll
            for (int off = 1; off < 32; off <<= 1) {
                int o = __shfl_down_sync(0xffffffffu, v, off);
                if (lane + off < 32) v += o;
            }
            if (lane == 0) ired[wid] = v;
            __syncthreads();
            int tail = 0;
            for (int w = wid + 1; w < 8; w++) tail += ired[w];
            int S = v + tail;
            ss[tid] = S;
            if (tid == 255) ss[256] = 0;
            __syncthreads();
            if (S >= TOPK && ss[tid + 1] < TOPK) {
                s_prefix = (unsigned)tid << 24;
                s_want = TOPK - ss[tid + 1];
            }
            __syncthreads();
        }
        unsigned prefix = s_prefix;
        int want = s_want;
        const unsigned btop = prefix >> 24;

        for (int j = tid; j < nPad; j += 256) {
            bool sel = (j < n) && ((f2key(sc[j]) >> 24) == btop);
            unsigned bal = __ballot_sync(0xffffffffu, sel);
            int base = 0;
            if (lane == 0 && bal) base = atomicAdd(&s_bcnt, __popc(bal));
            base = __shfl_sync(0xffffffffu, base, 0);
            if (sel) clist[base + __popc(bal & ((1u << lane) - 1u))] = j;
        }
        __syncthreads();
        const int B = s_bcnt;
        const int BPad = (B + 255) & ~255;

#pragma unroll
        for (int d = 2; d >= 0; d--) {
            hist[tid] = 0;
            __syncthreads();
            const int shift = d * 8;
            const unsigned pmask = 0xFFFFFFFFu << (shift + 8);
            for (int i = tid; i < BPad; i += 256) {
                int b = -1;
                if (i < B) {
                    unsigned k = f2key(sc[clist[i]]);
                    if ((k & pmask) == prefix) b = (int)((k >> shift) & 255u);
                }
                unsigned same = __match_any_sync(0xffffffffu, b);
                if (b >= 0 && lane == (__ffs(same) - 1)) atomicAdd(&hist[b], __popc(same));
            }
            __syncthreads();
            int v = hist[tid];
#pragma unroll
            for (int off = 1; off < 32; off <<= 1) {
                int o = __shfl_down_sync(0xffffffffu, v, off);
                if (lane + off < 32) v += o;
            }
            if (lane == 0) ired[wid] = v;
            __syncthreads();
            int tail = 0;
            for (int w = wid + 1; w < 8; w++) tail += ired[w];
            int S = v + tail;
            ss[tid] = S;
            __syncthreads();
            if (S >= want && ss[tid + 1] < want) {
                s_prefix = prefix | ((unsigned)tid << shift);
                s_want = want - ss[tid + 1];
            }
            __syncthreads();
            prefix = s_prefix;
            want = s_want;
            __syncthreads();
        }
        T = prefix;
        r = want;

        for (int j = tid; j < nPad; j += 256) {
            bool sel = false;
            float f = 0.f;
            unsigned k = 0;
            if (j < n) { f = sc[j]; k = f2key(f); sel = (k > T); }
            unsigned bal = __ballot_sync(0xffffffffu, sel);
            int base = 0;
            if (lane == 0 && bal) base = atomicAdd(&s_cnt, __popc(bal));
            base = __shfl_sync(0xffffffffu, base, 0);
            if (sel) {
                int pos = base + __popc(bal & ((1u << lane) - 1u));
                sidx[pos] = j; sw[pos] = expf(f - m);
            }
            if (j < n && k == T) {
                int p = atomicAdd(&s_tcnt, 1);
                if (p < 64) tlist[p] = j;
            }
        }
        __syncthreads();
        if (tid < s_tcnt && tid < 64) {
            int j = tlist[tid];
            int rank = 0;
            int tc = min(s_tcnt, 64);
            for (int t = 0; t < tc; t++) rank += (tlist[t] < j);
            if (rank < r) {
                int p = atomicAdd(&s_cnt, 1);
                sidx[p] = j; sw[p] = expf(sc[j] - m);
            }
        }
    } else {
        for (int j = tid; j < nPad; j += 256) {
            bool sel = (j < n);
            unsigned bal = __ballot_sync(0xffffffffu, sel);
            int base = 0;
            if (lane == 0 && bal) base = atomicAdd(&s_cnt, __popc(bal));
            base = __shfl_sync(0xffffffffu, base, 0);
            if (sel) {
                int pos = base + __popc(bal & ((1u << lane) - 1u));
                sidx[pos] = j; sw[pos] = expf(sc[j] - m);
            }
        }
    }
    __syncthreads();
    const int ns = min(s_cnt, 256);

    float z = 0.f;
    for (int p = tid; p < ns; p += 256) z += sw[p];
#pragma unroll
    for (int o = 16; o; o >>= 1) z += __shfl_xor_sync(0xffffffffu, z, o);
    if (lane == 0) fred[wid] = z;
    __syncthreads();
    if (tid == 0) {
        float t = 0.f;
        for (int w = 0; w < 8; w++) t += fred[w];
        s_z = t;
    }
    __syncthreads();
    const float Z = s_z;

    const int d = tid & 63, cg2 = tid >> 6;
    const float* vb = qkv + 2 * CDIM + h * HD + d;
    float a0 = 0.f, a1 = 0.f, a2 = 0.f, a3 = 0.f;
    int p = cg2;
    for (; p + 12 < ns; p += 16) {
        a0 = __fmaf_rn(sw[p],      vb[(size_t)sidx[p]      * C3], a0);
        a1 = __fmaf_rn(sw[p + 4],  vb[(size_t)sidx[p + 4]  * C3], a1);
        a2 = __fmaf_rn(sw[p + 8],  vb[(size_t)sidx[p + 8]  * C3], a2);
        a3 = __fmaf_rn(sw[p + 12], vb[(size_t)sidx[p + 12] * C3], a3);
    }
    for (; p < ns; p += 4)
        a0 = __fmaf_rn(sw[p], vb[(size_t)sidx[p] * C3], a0);
    yacc[cg2][d] = (a0 + a1) + (a2 + a3);
    __syncthreads();
    if (tid < 64) {
        float y = (yacc[0][tid] + yacc[1][tid]) + (yacc[2][tid] + yacc[3][tid]);
        ctx[(size_t)q * CDIM + h * HD + tid] = y / Z;
    }
}

// ------------------------------- launcher --------------------------------------
extern "C" void kernel_launch(void* const* d_in, const int* in_sizes, int n_in,
                              void* d_out, int out_size)
{
    (void)in_sizes; (void)n_in; (void)out_size;
    const float* x      = (const float*)d_in[0];
    const float* w_qkv  = (const float*)d_in[1];
    const float* w_proj = (const float*)d_in[2];
    float* out = (float*)d_out;

    float *qkv, *gq, *gk, *gsc, *gctx, *gcos, *gsin;
    __nv_bfloat16 *xhi, *xlo, *wvhi, *wvlo, *wphi, *wplo, *chi, *clo;
    cudaGetSymbolAddress((void**)&qkv,  g_qkv);
    cudaGetSymbolAddress((void**)&gq,   g_q);
    cudaGetSymbolAddress((void**)&gk,   g_k);
    cudaGetSymbolAddress((void**)&gsc,  g_sc);
    cudaGetSymbolAddress((void**)&gctx, g_ctx);
    cudaGetSymbolAddress((void**)&gcos, g_cos);
    cudaGetSymbolAddress((void**)&gsin, g_sin);
    cudaGetSymbolAddress((void**)&xhi,  g_xhi);
    cudaGetSymbolAddress((void**)&xlo,  g_xlo);
    cudaGetSymbolAddress((void**)&wvhi, g_wvhi);
    cudaGetSymbolAddress((void**)&wvlo, g_wvlo);
    cudaGetSymbolAddress((void**)&wphi, g_wphi);
    cudaGetSymbolAddress((void**)&wplo, g_wplo);
    cudaGetSymbolAddress((void**)&chi,  g_chi);
    cudaGetSymbolAddress((void**)&clo,  g_clo);

    static bool attr_done = false;
    const int scores_smem = 2 * 64 * 129 * (int)sizeof(float);
    if (!attr_done) {
        cudaFuncSetAttribute(scores_kernel_h,
                             cudaFuncAttributeMaxDynamicSharedMemorySize, scores_smem);
        attr_done = true;
    }

    build_tables<<<(SLEN * 32 + 255) / 256, 256>>>(gcos, gsin);

    // splits for the value-path tensor GEMMs
    split_bf16<<<SLEN * CDIM / 4 / 256, 256>>>(x, xhi, xlo, SLEN * CDIM);
    split_bf16<<<CDIM * CDIM / 4 / 256, 256>>>(w_qkv + 2 * CDIM * CDIM, wvhi, wvlo, CDIM * CDIM);
    split_bf16<<<CDIM * CDIM / 4 / 256, 256>>>(w_proj, wphi, wplo, CDIM * CDIM);

    // 1a) q,k = x @ w_qkv[0:2048]^T  (fp32, bitwise-frozen; ldc=3072)
    sgemm_nt_fast<<<dim3(2048 / 128, SLEN / 128), 256>>>(x, w_qkv, qkv, 2048, CDIM, C3);
    // 1b) v = x @ w_qkv[2048:3072]^T  (wmma bf16x3, value path)
    gemm_wmma_bf16x3<<<dim3(CDIM / 64, SLEN / 64), 128>>>(
        xhi, xlo, wvhi, wvlo, qkv + 2 * CDIM, C3, CDIM);

    // 2) RoPE + normalize q,k
    {
        int warps = 2 * NH * SLEN;
        int blocks = (warps * 32 + 255) / 256;
        rope_norm_kernel<<<blocks, 256>>>(qkv, gcos, gsin, gq, gk);
    }

    // 3+4) per-head pairs: scores_h then topk_h — one head's scores (16 MB)
    //      stay L2-resident between producer and consumer.
    for (int h = 0; h < NH; h++) {
        scores_kernel_h<<<dim3(SLEN / 128, SLEN / 128), 256, scores_smem>>>(gq, gk, gsc, h);
        topk_av_kernel_h<<<SLEN, 256>>>(gsc, qkv, gctx, h);
    }

    // 5) out = ctx @ w_proj^T  (wmma bf16x3, value path)
    split_bf16<<<SLEN * CDIM / 4 / 256, 256>>>(gctx, chi, clo, SLEN * CDIM);
    gemm_wmma_bf16x3<<<dim3(CDIM / 64, SLEN / 64), 128>>>(
        chi, clo, wphi, wplo, out, CDIM, CDIM);
}

// round 16
// speedup vs baseline: 1.1136x; 1.1136x over previous
#include <cuda_runtime.h>
#include <cuda_bf16.h>
#include <mma.h>
#include <cstdint>
#include <stdint.h>
#include <math.h>
#include <float.h>

using namespace nvcuda;

#define SLEN 2048
#define CDIM 1024
#define NH   16
#define HD   64
#define TOPK 128
#define C3   3072

// ---------------- scratch (static device globals; no allocs allowed) ----------
__device__ float g_qkv[SLEN * C3];
__device__ float g_q[NH * SLEN * HD];
__device__ float g_k[NH * SLEN * HD];
__device__ float g_sc[(size_t)NH * SLEN * SLEN];
__device__ float g_ctx[SLEN * CDIM];
__device__ float g_cos[SLEN * 32];
__device__ float g_sin[SLEN * 32];
__device__ __nv_bfloat16 g_xhi[SLEN * CDIM];
__device__ __nv_bfloat16 g_xlo[SLEN * CDIM];
__device__ __nv_bfloat16 g_wvhi[CDIM * CDIM];
__device__ __nv_bfloat16 g_wvlo[CDIM * CDIM];
__device__ __nv_bfloat16 g_wphi[CDIM * CDIM];
__device__ __nv_bfloat16 g_wplo[CDIM * CDIM];
__device__ __nv_bfloat16 g_chi[SLEN * CDIM];
__device__ __nv_bfloat16 g_clo[SLEN * CDIM];

// ---------------- RoPE trig tables (reference op-by-op fp32 rounding) ----------
__global__ void build_tables(float* __restrict__ ct, float* __restrict__ st)
{
    int t = blockIdx.x * blockDim.x + threadIdx.x;
    if (t >= SLEN * 32) return;
    int i = t & 31, s = t >> 5;
    double te = (double)(2 * i) / 64.0;
    float b = (float)pow(10000.0, te);
    float inv = __fdiv_rn(1.0f, b);
    float ang = __fmul_rn((float)s, inv);
    ct[t] = (float)cos((double)ang);
    st[t] = (float)sin((double)ang);
}

// ---------------- fp32 -> bf16 hi/lo split --------------------------------------
__global__ void split_bf16(const float* __restrict__ src,
                           __nv_bfloat16* __restrict__ hi,
                           __nv_bfloat16* __restrict__ lo, int n)
{
    int i = (blockIdx.x * 256 + threadIdx.x) * 4;
    if (i >= n) return;
    float4 v = *(const float4*)(src + i);
    float vv[4] = {v.x, v.y, v.z, v.w};
    __nv_bfloat16 h[4], l[4];
#pragma unroll
    for (int e = 0; e < 4; e++) {
        h[e] = __float2bfloat16(vv[e]);
        l[e] = __float2bfloat16(vv[e] - __bfloat162float(h[e]));
    }
    *(uint2*)(hi + i) = *(uint2*)h;
    *(uint2*)(lo + i) = *(uint2*)l;
}

// ---------------- fast NT SGEMM (bitwise-frozen ascending-k FMA chain) ---------
__global__ __launch_bounds__(256, 2) void sgemm_nt_fast(const float* __restrict__ A,
                                                        const float* __restrict__ B,
                                                        float* __restrict__ Cmat,
                                                        int N, int K, int ldc)
{
    __shared__ float As[2][16][128];
    __shared__ float Bs[2][16][128];
    const int tid = threadIdx.x;
    const int bm = blockIdx.y * 128;
    const int bn = blockIdx.x * 128;
    const int tx = tid & 15;
    const int ty = tid >> 4;
    const int lr = tid >> 1;
    const int lc = (tid & 1) * 8;

    const float* Ap = A + (size_t)(bm + lr) * K + lc;
    const float* Bp = B + (size_t)(bn + lr) * K + lc;

    float acc[8][8] = {};
    float4 pa0 = *(const float4*)Ap;
    float4 pa1 = *(const float4*)(Ap + 4);
    float4 pb0 = *(const float4*)Bp;
    float4 pb1 = *(const float4*)(Bp + 4);
    int buf = 0;
    As[0][lc + 0][lr] = pa0.x; As[0][lc + 1][lr] = pa0.y;
    As[0][lc + 2][lr] = pa0.z; As[0][lc + 3][lr] = pa0.w;
    As[0][lc + 4][lr] = pa1.x; As[0][lc + 5][lr] = pa1.y;
    As[0][lc + 6][lr] = pa1.z; As[0][lc + 7][lr] = pa1.w;
    Bs[0][lc + 0][lr] = pb0.x; Bs[0][lc + 1][lr] = pb0.y;
    Bs[0][lc + 2][lr] = pb0.z; Bs[0][lc + 3][lr] = pb0.w;
    Bs[0][lc + 4][lr] = pb1.x; Bs[0][lc + 5][lr] = pb1.y;
    Bs[0][lc + 6][lr] = pb1.z; Bs[0][lc + 7][lr] = pb1.w;
    __syncthreads();

    const int ntiles = K >> 4;
    for (int kt = 0; kt < ntiles; kt++) {
        const bool more = (kt + 1 < ntiles);
        if (more) {
            const float* An = Ap + (size_t)(kt + 1) * 16;
            const float* Bn = Bp + (size_t)(kt + 1) * 16;
            pa0 = *(const float4*)An; pa1 = *(const float4*)(An + 4);
            pb0 = *(const float4*)Bn; pb1 = *(const float4*)(Bn + 4);
        }
#pragma unroll
        for (int k = 0; k < 16; k++) {
            float4 a0 = *(const float4*)&As[buf][k][ty * 8];
            float4 a1 = *(const float4*)&As[buf][k][ty * 8 + 4];
            float4 b0 = *(const float4*)&Bs[buf][k][tx * 8];
            float4 b1 = *(const float4*)&Bs[buf][k][tx * 8 + 4];
            float av[8] = {a0.x, a0.y, a0.z, a0.w, a1.x, a1.y, a1.z, a1.w};
            float bv[8] = {b0.x, b0.y, b0.z, b0.w, b1.x, b1.y, b1.z, b1.w};
#pragma unroll
            for (int i = 0; i < 8; i++)
#pragma unroll
                for (int j = 0; j < 8; j++)
                    acc[i][j] = __fmaf_rn(av[i], bv[j], acc[i][j]);
        }
        if (more) {
            buf ^= 1;
            As[buf][lc + 0][lr] = pa0.x; As[buf][lc + 1][lr] = pa0.y;
            As[buf][lc + 2][lr] = pa0.z; As[buf][lc + 3][lr] = pa0.w;
            As[buf][lc + 4][lr] = pa1.x; As[buf][lc + 5][lr] = pa1.y;
            As[buf][lc + 6][lr] = pa1.z; As[buf][lc + 7][lr] = pa1.w;
            Bs[buf][lc + 0][lr] = pb0.x; Bs[buf][lc + 1][lr] = pb0.y;
            Bs[buf][lc + 2][lr] = pb0.z; Bs[buf][lc + 3][lr] = pb0.w;
            Bs[buf][lc + 4][lr] = pb1.x; Bs[buf][lc + 5][lr] = pb1.y;
            Bs[buf][lc + 6][lr] = pb1.z; Bs[buf][lc + 7][lr] = pb1.w;
            __syncthreads();
        }
    }
    (void)N;
#pragma unroll
    for (int i = 0; i < 8; i++) {
        float* Cp = Cmat + (size_t)(bm + ty * 8 + i) * ldc + bn + tx * 8;
        *(float4*)Cp       = make_float4(acc[i][0], acc[i][1], acc[i][2], acc[i][3]);
        *(float4*)(Cp + 4) = make_float4(acc[i][4], acc[i][5], acc[i][6], acc[i][7]);
    }
}

// ================= wmma bf16x3 GEMM: 128x128 tile, 8 warps, 32x64 warp tile ====
__global__ __launch_bounds__(256) void gemm_wmma_bf16x3(
    const __nv_bfloat16* __restrict__ Ahi, const __nv_bfloat16* __restrict__ Alo,
    const __nv_bfloat16* __restrict__ Bhi, const __nv_bfloat16* __restrict__ Blo,
    float* __restrict__ Cmat, int ldc, int K)
{
    extern __shared__ __nv_bfloat16 wsm[];
    __nv_bfloat16 (*sAhi)[72] = (__nv_bfloat16(*)[72])wsm;
    __nv_bfloat16 (*sAlo)[72] = (__nv_bfloat16(*)[72])(wsm + 128 * 72);
    __nv_bfloat16 (*sBhi)[72] = (__nv_bfloat16(*)[72])(wsm + 2 * 128 * 72);
    __nv_bfloat16 (*sBlo)[72] = (__nv_bfloat16(*)[72])(wsm + 3 * 128 * 72);

    const int tid = threadIdx.x;
    const int wid = tid >> 5;
    const int bm = blockIdx.y * 128;
    const int bn = blockIdx.x * 128;
    const int wm = (wid >> 1) * 32;     // 4 row groups of 32
    const int wn = (wid & 1) * 64;      // 2 col groups of 64

    wmma::fragment<wmma::accumulator, 16, 16, 16, float> acc[2][4];
#pragma unroll
    for (int i = 0; i < 2; i++)
#pragma unroll
        for (int j = 0; j < 4; j++)
            wmma::fill_fragment(acc[i][j], 0.0f);

    const int nchunks = K >> 6;
    for (int kc = 0; kc < nchunks; kc++) {
        const int kofs = kc * 64;
#pragma unroll
        for (int i = 0; i < 4; i++) {      // 1024 uint4 per buffer / 256 threads
            int id = tid + i * 256;
            int row = id >> 3, col = (id & 7) * 8;
            *(uint4*)&sAhi[row][col] = *(const uint4*)(Ahi + (size_t)(bm + row) * K + kofs + col);
            *(uint4*)&sAlo[row][col] = *(const uint4*)(Alo + (size_t)(bm + row) * K + kofs + col);
            *(uint4*)&sBhi[row][col] = *(const uint4*)(Bhi + (size_t)(bn + row) * K + kofs + col);
            *(uint4*)&sBlo[row][col] = *(const uint4*)(Blo + (size_t)(bn + row) * K + kofs + col);
        }
        __syncthreads();

#pragma unroll
        for (int kk = 0; kk < 4; kk++) {
            wmma::fragment<wmma::matrix_a, 16, 16, 16, __nv_bfloat16, wmma::row_major> ahi[2], alo[2];
            wmma::fragment<wmma::matrix_b, 16, 16, 16, __nv_bfloat16, wmma::col_major> bhi[4], blo[4];
#pragma unroll
            for (int i = 0; i < 2; i++) {
                wmma::load_matrix_sync(ahi[i], &sAhi[wm + 16 * i][kk * 16], 72);
                wmma::load_matrix_sync(alo[i], &sAlo[wm + 16 * i][kk * 16], 72);
            }
#pragma unroll
            for (int j = 0; j < 4; j++) {
                wmma::load_matrix_sync(bhi[j], &sBhi[wn + 16 * j][kk * 16], 72);
                wmma::load_matrix_sync(blo[j], &sBlo[wn + 16 * j][kk * 16], 72);
            }
#pragma unroll
            for (int i = 0; i < 2; i++)
#pragma unroll
                for (int j = 0; j < 4; j++) {
                    wmma::mma_sync(acc[i][j], ahi[i], bhi[j], acc[i][j]);
                    wmma::mma_sync(acc[i][j], ahi[i], blo[j], acc[i][j]);
                    wmma::mma_sync(acc[i][j], alo[i], bhi[j], acc[i][j]);
                }
        }
        __syncthreads();
    }

#pragma unroll
    for (int i = 0; i < 2; i++)
#pragma unroll
        for (int j = 0; j < 4; j++)
            wmma::store_matrix_sync(Cmat + (size_t)(bm + wm + 16 * i) * ldc + bn + wn + 16 * j,
                                    acc[i][j], ldc, wmma::mem_row_major);
}
#define WMMA_SMEM (4 * 128 * 72 * (int)sizeof(__nv_bfloat16))

// ---------------- RoPE + L2 normalize (bitwise-frozen) -------------------------
__global__ void rope_norm_kernel(const float* __restrict__ qkv,
                                 const float* __restrict__ ct,
                                 const float* __restrict__ st,
                                 float* __restrict__ gq, float* __restrict__ gk)
{
    __shared__ float buf[8][64];
    __shared__ float nrm[8];
    const int w = threadIdx.x >> 5;
    const int gw = (blockIdx.x * blockDim.x + threadIdx.x) >> 5;
    const int lane = threadIdx.x & 31;
    if (gw >= 2 * NH * SLEN) return;
    const int which = (gw >= NH * SLEN) ? 1 : 0;
    const int rem = which ? gw - NH * SLEN : gw;
    const int h = rem >> 11;
    const int s = rem & (SLEN - 1);

    const float* src = qkv + (size_t)s * C3 + which * CDIM + h * HD;
    float x0 = src[2 * lane];
    float x1 = src[2 * lane + 1];

    float cv = ct[s * 32 + lane];
    float sv = st[s * 32 + lane];

    float r0 = __fadd_rn(__fmul_rn(x0, cv), __fmul_rn(-x1, sv));
    float r1 = __fadd_rn(__fmul_rn(x1, cv), __fmul_rn(x0, sv));

    buf[w][2 * lane]     = r0;
    buf[w][2 * lane + 1] = r1;
    __syncwarp();
    if (lane == 0) {
        float l0 = 0.f, l1 = 0.f, l2 = 0.f, l3 = 0.f;
        for (int t = 0; t < 16; t++) {
            float v0 = buf[w][4 * t + 0];
            float v1 = buf[w][4 * t + 1];
            float v2 = buf[w][4 * t + 2];
            float v3 = buf[w][4 * t + 3];
            l0 = __fadd_rn(l0, __fmul_rn(v0, v0));
            l1 = __fadd_rn(l1, __fmul_rn(v1, v1));
            l2 = __fadd_rn(l2, __fmul_rn(v2, v2));
            l3 = __fadd_rn(l3, __fmul_rn(v3, v3));
        }
        float ssum = __fadd_rn(__fadd_rn(l0, l1), __fadd_rn(l2, l3));
        nrm[w] = fmaxf(__fsqrt_rn(ssum), 1e-12f);
    }
    __syncwarp();
    const float nv = nrm[w];

    float* dst = (which ? gk : gq) + ((size_t)h * SLEN + s) * HD;
    dst[2 * lane]     = __fdiv_rn(r0, nv);
    dst[2 * lane + 1] = __fdiv_rn(r1, nv);
}

// ---------------- causal scores (bitwise-frozen chain) -------------------------
__global__ __launch_bounds__(256) void scores_kernel(const float* __restrict__ gq,
                                                     const float* __restrict__ gk,
                                                     float* __restrict__ gs)
{
    const int h = blockIdx.z;
    const int jb = blockIdx.x * 128;
    const int qb = blockIdx.y * 128;
    if (jb > qb) return;

    extern __shared__ float smemf[];
    float (*Qs)[129] = (float(*)[129])smemf;
    float (*Ks)[129] = (float(*)[129])(smemf + 64 * 129);

    const int tid = threadIdx.x;
    const float* qp = gq + ((size_t)h * SLEN + qb) * HD;
    const float* kp = gk + ((size_t)h * SLEN + jb) * HD;
#pragma unroll
    for (int i = 0; i < 32; i++) {
        int idx = tid + i * 256;
        int r = idx >> 6, c = idx & 63;
        Qs[c][r] = qp[idx];
        Ks[c][r] = kp[idx];
    }
    __syncthreads();

    const int tx = tid & 15, ty = tid >> 4;
    float acc[8][8] = {};
#pragma unroll
    for (int k = 0; k < 64; k++) {
        float a[8], b[8];
#pragma unroll
        for (int i = 0; i < 8; i++) a[i] = Qs[k][ty + 16 * i];
#pragma unroll
        for (int j = 0; j < 8; j++) b[j] = Ks[k][tx + 16 * j];
#pragma unroll
        for (int i = 0; i < 8; i++)
#pragma unroll
            for (int j = 0; j < 8; j++)
                acc[i][j] = __fmaf_rn(a[i], b[j], acc[i][j]);
    }
#pragma unroll
    for (int i = 0; i < 8; i++) {
        float* outp = gs + ((size_t)h * SLEN + qb + ty + 16 * i) * SLEN + jb + tx;
#pragma unroll
        for (int j = 0; j < 8; j++)
            outp[16 * j] = __fmul_rn(acc[i][j], 0.125f);
    }
}

// ---------------- helpers ------------------------------------------------------
__device__ __forceinline__ unsigned f2key(float f)
{
    unsigned u = __float_as_uint(f);
    return (u & 0x80000000u) ? ~u : (u | 0x80000000u);
}

// ---------------- hard top-k (two-level radix) + softmax + AV, 512 threads -----
__global__ __launch_bounds__(512) void topk_av_kernel(const float* __restrict__ gs,
                                                      const float* __restrict__ qkv,
                                                      float* __restrict__ ctx)
{
    __shared__ float sc[SLEN];
    __shared__ int   clist[SLEN];
    __shared__ float fred[16];
    __shared__ int   ired[16];
    __shared__ int   hist[256];
    __shared__ int   ss[257];
    __shared__ float s_max;
    __shared__ float s_z;
    __shared__ unsigned s_prefix;
    __shared__ int   s_want;
    __shared__ int   s_cnt;
    __shared__ int   s_tcnt;
    __shared__ int   s_bcnt;
    __shared__ int   tlist[64];
    __shared__ int   sidx[256];
    __shared__ float sw[256];
    __shared__ float yacc[8][64];

    const int row = blockIdx.x;
    const int h = row >> 11;
    const int q = (SLEN - 1) - (row & (SLEN - 1));   // long rows first
    const int n = q + 1;
    const int tid = threadIdx.x;
    const int lane = tid & 31, wid = tid >> 5;       // 16 warps
    const bool doSel = (n > TOPK);

    const float* src = gs + ((size_t)h * SLEN + q) * SLEN;

    if (tid < 256) hist[tid] = 0;
    if (tid == 0) { s_cnt = 0; s_tcnt = 0; s_bcnt = 0; }
    __syncthreads();

    // ===== scan 1: fused load + max + top-byte histogram (2048 floats / sweep) ==
    float m = -FLT_MAX;
    {
        int j0 = tid * 4;
        float4 v = make_float4(0.f, 0.f, 0.f, 0.f);
        if (j0 + 3 < n) {
            v = *(const float4*)(src + j0);
        } else if (j0 < n) {
            v.x = src[j0];
            if (j0 + 1 < n) v.y = src[j0 + 1];
            if (j0 + 2 < n) v.z = src[j0 + 2];
            if (j0 + 3 < n) v.w = src[j0 + 3];
        }
        if (j0 < n) {
            sc[j0] = v.x;
            if (j0 + 1 < n) sc[j0 + 1] = v.y;
            if (j0 + 2 < n) sc[j0 + 2] = v.z;
            if (j0 + 3 < n) sc[j0 + 3] = v.w;
        }
        float vv[4] = {v.x, v.y, v.z, v.w};
#pragma unroll
        for (int e = 0; e < 4; e++) {
            bool ok = (j0 + e) < n;
            if (ok) m = fmaxf(m, vv[e]);
            if (doSel) {
                int b = ok ? (int)(f2key(vv[e]) >> 24) : -1;
                unsigned same = __match_any_sync(0xffffffffu, b);
                if (b >= 0 && lane == (__ffs(same) - 1)) atomicAdd(&hist[b], __popc(same));
            }
        }
    }
#pragma unroll
    for (int o = 16; o; o >>= 1) m = fmaxf(m, __shfl_xor_sync(0xffffffffu, m, o));
    if (lane == 0) fred[wid] = m;
    __syncthreads();
    if (tid == 0) {
        float mm = fred[0];
        for (int w = 1; w < 16; w++) mm = fmaxf(mm, fred[w]);
        s_max = mm;
    }
    __syncthreads();
    m = s_max;

    const int nPad = (n + 511) & ~511;
    unsigned T = 0;
    int r = 0;

    if (doSel) {
        // ===== pass 1: boundary top byte (first 256 threads scan hist) =====
        {
            int S = 0;
            if (tid < 256) {
                int v = hist[tid];
#pragma unroll
                for (int off = 1; off < 32; off <<= 1) {
                    int o = __shfl_down_sync(0xffffffffu, v, off);
                    if (lane + off < 32) v += o;
                }
                if (lane == 0) ired[wid] = v;
                S = v;
            }
            __syncthreads();
            if (tid < 256) {
                int tail = 0;
                for (int w = wid + 1; w < 8; w++) tail += ired[w];
                S += tail;
                ss[tid] = S;
                if (tid == 255) ss[256] = 0;
            }
            __syncthreads();
            if (tid < 256 && S >= TOPK && ss[tid + 1] < TOPK) {
                s_prefix = (unsigned)tid << 24;
                s_want = TOPK - ss[tid + 1];
            }
            __syncthreads();
        }
        unsigned prefix = s_prefix;
        int want = s_want;
        const unsigned btop = prefix >> 24;

        // ===== scan 2: compact boundary-bucket indices =====
        for (int j = tid; j < nPad; j += 512) {
            bool sel = (j < n) && ((f2key(sc[j]) >> 24) == btop);
            unsigned bal = __ballot_sync(0xffffffffu, sel);
            int base = 0;
            if (lane == 0 && bal) base = atomicAdd(&s_bcnt, __popc(bal));
            base = __shfl_sync(0xffffffffu, base, 0);
            if (sel) clist[base + __popc(bal & ((1u << lane) - 1u))] = j;
        }
        __syncthreads();
        const int B = s_bcnt;
        const int BPad = (B + 511) & ~511;

        // ===== passes 2-4 over bucket list =====
#pragma unroll
        for (int d = 2; d >= 0; d--) {
            if (tid < 256) hist[tid] = 0;
            __syncthreads();
            const int shift = d * 8;
            const unsigned pmask = 0xFFFFFFFFu << (shift + 8);
            for (int i = tid; i < BPad; i += 512) {
                int b = -1;
                if (i < B) {
                    unsigned k = f2key(sc[clist[i]]);
                    if ((k & pmask) == prefix) b = (int)((k >> shift) & 255u);
                }
                unsigned same = __match_any_sync(0xffffffffu, b);
                if (b >= 0 && lane == (__ffs(same) - 1)) atomicAdd(&hist[b], __popc(same));
            }
            __syncthreads();
            int S = 0;
            if (tid < 256) {
                int v = hist[tid];
#pragma unroll
                for (int off = 1; off < 32; off <<= 1) {
                    int o = __shfl_down_sync(0xffffffffu, v, off);
                    if (lane + off < 32) v += o;
                }
                if (lane == 0) ired[wid] = v;
                S = v;
            }
            __syncthreads();
            if (tid < 256) {
                int tail = 0;
                for (int w = wid + 1; w < 8; w++) tail += ired[w];
                S += tail;
                ss[tid] = S;
            }
            __syncthreads();
            if (tid < 256 && S >= want && ss[tid + 1] < want) {
                s_prefix = prefix | ((unsigned)tid << shift);
                s_want = want - ss[tid + 1];
            }
            __syncthreads();
            prefix = s_prefix;
            want = s_want;
            __syncthreads();
        }
        T = prefix;
        r = want;

        // ===== scan 3: final selection + tie gather =====
        for (int j = tid; j < nPad; j += 512) {
            bool sel = false;
            float f = 0.f;
            unsigned k = 0;
            if (j < n) { f = sc[j]; k = f2key(f); sel = (k > T); }
            unsigned bal = __ballot_sync(0xffffffffu, sel);
            int base = 0;
            if (lane == 0 && bal) base = atomicAdd(&s_cnt, __popc(bal));
            base = __shfl_sync(0xffffffffu, base, 0);
            if (sel) {
                int pos = base + __popc(bal & ((1u << lane) - 1u));
                sidx[pos] = j; sw[pos] = expf(f - m);
            }
            if (j < n && k == T) {
                int p = atomicAdd(&s_tcnt, 1);
                if (p < 64) tlist[p] = j;
            }
        }
        __syncthreads();
        if (tid < s_tcnt && tid < 64) {
            int j = tlist[tid];
            int rank = 0;
            int tc = min(s_tcnt, 64);
            for (int t = 0; t < tc; t++) rank += (tlist[t] < j);
            if (rank < r) {
                int p = atomicAdd(&s_cnt, 1);
                sidx[p] = j; sw[p] = expf(sc[j] - m);
            }
        }
    } else {
        for (int j = tid; j < nPad; j += 512) {
            bool sel = (j < n);
            unsigned bal = __ballot_sync(0xffffffffu, sel);
            int base = 0;
            if (lane == 0 && bal) base = atomicAdd(&s_cnt, __popc(bal));
            base = __shfl_sync(0xffffffffu, base, 0);
            if (sel) {
                int pos = base + __popc(bal & ((1u << lane) - 1u));
                sidx[pos] = j; sw[pos] = expf(sc[j] - m);
            }
        }
    }
    __syncthreads();
    const int ns = min(s_cnt, 256);

    // ---- Z ----
    float z = 0.f;
    for (int p = tid; p < ns; p += 512) z += sw[p];
#pragma unroll
    for (int o = 16; o; o >>= 1) z += __shfl_xor_sync(0xffffffffu, z, o);
    if (lane == 0) fred[wid] = z;
    __syncthreads();
    if (tid == 0) {
        float t = 0.f;
        for (int w = 0; w < 16; w++) t += fred[w];
        s_z = t;
    }
    __syncthreads();
    const float Z = s_z;

    // ---- y = (1/Z) * sum_p w_p * v[idx_p, :]  (8 groups x 64 dims, MLP 4) ----
    const int d = tid & 63, cg2 = tid >> 6;            // cg2 in 0..7
    const float* vb = qkv + 2 * CDIM + h * HD + d;
    float a0 = 0.f, a1 = 0.f, a2 = 0.f, a3 = 0.f;
    int p = cg2;
    for (; p + 24 < ns; p += 32) {
        a0 = __fmaf_rn(sw[p],      vb[(size_t)sidx[p]      * C3], a0);
        a1 = __fmaf_rn(sw[p + 8],  vb[(size_t)sidx[p + 8]  * C3], a1);
        a2 = __fmaf_rn(sw[p + 16], vb[(size_t)sidx[p + 16] * C3], a2);
        a3 = __fmaf_rn(sw[p + 24], vb[(size_t)sidx[p + 24] * C3], a3);
    }
    for (; p < ns; p += 8)
        a0 = __fmaf_rn(sw[p], vb[(size_t)sidx[p] * C3], a0);
    yacc[cg2][d] = (a0 + a1) + (a2 + a3);
    __syncthreads();
    if (tid < 64) {
        float y = ((yacc[0][tid] + yacc[1][tid]) + (yacc[2][tid] + yacc[3][tid]))
                + ((yacc[4][tid] + yacc[5][tid]) + (yacc[6][tid] + yacc[7][tid]));
        ctx[(size_t)q * CDIM + h * HD + tid] = y / Z;
    }
}

// ------------------------------- launcher --------------------------------------
extern "C" void kernel_launch(void* const* d_in, const int* in_sizes, int n_in,
                              void* d_out, int out_size)
{
    (void)in_sizes; (void)n_in; (void)out_size;
    const float* x      = (const float*)d_in[0];
    const float* w_qkv  = (const float*)d_in[1];
    const float* w_proj = (const float*)d_in[2];
    float* out = (float*)d_out;

    float *qkv, *gq, *gk, *gsc, *gctx, *gcos, *gsin;
    __nv_bfloat16 *xhi, *xlo, *wvhi, *wvlo, *wphi, *wplo, *chi, *clo;
    cudaGetSymbolAddress((void**)&qkv,  g_qkv);
    cudaGetSymbolAddress((void**)&gq,   g_q);
    cudaGetSymbolAddress((void**)&gk,   g_k);
    cudaGetSymbolAddress((void**)&gsc,  g_sc);
    cudaGetSymbolAddress((void**)&gctx, g_ctx);
    cudaGetSymbolAddress((void**)&gcos, g_cos);
    cudaGetSymbolAddress((void**)&gsin, g_sin);
    cudaGetSymbolAddress((void**)&xhi,  g_xhi);
    cudaGetSymbolAddress((void**)&xlo,  g_xlo);
    cudaGetSymbolAddress((void**)&wvhi, g_wvhi);
    cudaGetSymbolAddress((void**)&wvlo, g_wvlo);
    cudaGetSymbolAddress((void**)&wphi, g_wphi);
    cudaGetSymbolAddress((void**)&wplo, g_wplo);
    cudaGetSymbolAddress((void**)&chi,  g_chi);
    cudaGetSymbolAddress((void**)&clo,  g_clo);

    static bool attr_done = false;
    const int scores_smem = 2 * 64 * 129 * (int)sizeof(float);
    if (!attr_done) {
        cudaFuncSetAttribute(scores_kernel,
                             cudaFuncAttributeMaxDynamicSharedMemorySize, scores_smem);
        cudaFuncSetAttribute(gemm_wmma_bf16x3,
                             cudaFuncAttributeMaxDynamicSharedMemorySize, WMMA_SMEM);
        attr_done = true;
    }

    build_tables<<<(SLEN * 32 + 255) / 256, 256>>>(gcos, gsin);

    split_bf16<<<SLEN * CDIM / 4 / 256, 256>>>(x, xhi, xlo, SLEN * CDIM);
    split_bf16<<<CDIM * CDIM / 4 / 256, 256>>>(w_qkv + 2 * CDIM * CDIM, wvhi, wvlo, CDIM * CDIM);
    split_bf16<<<CDIM * CDIM / 4 / 256, 256>>>(w_proj, wphi, wplo, CDIM * CDIM);

    // 1a) q,k = x @ w_qkv[0:2048]^T  (fp32, bitwise-frozen; ldc=3072)
    sgemm_nt_fast<<<dim3(2048 / 128, SLEN / 128), 256>>>(x, w_qkv, qkv, 2048, CDIM, C3);
    // 1b) v = x @ w_qkv[2048:3072]^T  (wmma bf16x3, value path)
    gemm_wmma_bf16x3<<<dim3(CDIM / 128, SLEN / 128), 256, WMMA_SMEM>>>(
        xhi, xlo, wvhi, wvlo, qkv + 2 * CDIM, C3, CDIM);

    // 2) RoPE + normalize q,k
    {
        int warps = 2 * NH * SLEN;
        int blocks = (warps * 32 + 255) / 256;
        rope_norm_kernel<<<blocks, 256>>>(qkv, gcos, gsin, gq, gk);
    }

    // 3) causal scores per head (monolithic)
    scores_kernel<<<dim3(SLEN / 128, SLEN / 128, NH), 256, scores_smem>>>(gq, gk, gsc);

    // 4) top-128 + softmax + A@V (512 threads)
    topk_av_kernel<<<NH * SLEN, 512>>>(gsc, qkv, gctx);

    // 5) out = ctx @ w_proj^T  (wmma bf16x3, value path)
    split_bf16<<<SLEN * CDIM / 4 / 256, 256>>>(gctx, chi, clo, SLEN * CDIM);
    gemm_wmma_bf16x3<<<dim3(CDIM / 128, SLEN / 128), 256, WMMA_SMEM>>>(
        chi, clo, wphi, wplo, out, CDIM, CDIM);
}

// round 17
// speedup vs baseline: 1.2707x; 1.1412x over previous
#include <cuda_runtime.h>
#include <cuda_bf16.h>
#include <mma.h>
#include <cstdint>
#include <stdint.h>
#include <math.h>
#include <float.h>

using namespace nvcuda;

#define SLEN 2048
#define CDIM 1024
#define NH   16
#define HD   64
#define TOPK 128
#define C3   3072

// ---------------- scratch (static device globals; no allocs allowed) ----------
__device__ float g_qkv[SLEN * C3];
__device__ float g_q[NH * SLEN * HD];
__device__ float g_k[NH * SLEN * HD];
__device__ float g_sc[(size_t)NH * SLEN * SLEN];
__device__ float g_ctx[SLEN * CDIM];
__device__ float g_cos[SLEN * 32];
__device__ float g_sin[SLEN * 32];
__device__ __nv_bfloat16 g_xhi[SLEN * CDIM];
__device__ __nv_bfloat16 g_xlo[SLEN * CDIM];
__device__ __nv_bfloat16 g_wvhi[CDIM * CDIM];
__device__ __nv_bfloat16 g_wvlo[CDIM * CDIM];
__device__ __nv_bfloat16 g_wphi[CDIM * CDIM];
__device__ __nv_bfloat16 g_wplo[CDIM * CDIM];
__device__ __nv_bfloat16 g_chi[SLEN * CDIM];
__device__ __nv_bfloat16 g_clo[SLEN * CDIM];

// ---------------- RoPE trig tables (reference op-by-op fp32 rounding) ----------
__global__ void build_tables(float* __restrict__ ct, float* __restrict__ st)
{
    int t = blockIdx.x * blockDim.x + threadIdx.x;
    if (t >= SLEN * 32) return;
    int i = t & 31, s = t >> 5;
    double te = (double)(2 * i) / 64.0;
    float b = (float)pow(10000.0, te);
    float inv = __fdiv_rn(1.0f, b);
    float ang = __fmul_rn((float)s, inv);
    ct[t] = (float)cos((double)ang);
    st[t] = (float)sin((double)ang);
}

// ---------------- fp32 -> bf16 hi/lo split --------------------------------------
__global__ void split_bf16(const float* __restrict__ src,
                           __nv_bfloat16* __restrict__ hi,
                           __nv_bfloat16* __restrict__ lo, int n)
{
    int i = (blockIdx.x * 256 + threadIdx.x) * 4;
    if (i >= n) return;
    float4 v = *(const float4*)(src + i);
    float vv[4] = {v.x, v.y, v.z, v.w};
    __nv_bfloat16 h[4], l[4];
#pragma unroll
    for (int e = 0; e < 4; e++) {
        h[e] = __float2bfloat16(vv[e]);
        l[e] = __float2bfloat16(vv[e] - __bfloat162float(h[e]));
    }
    *(uint2*)(hi + i) = *(uint2*)h;
    *(uint2*)(lo + i) = *(uint2*)l;
}

// ---------------- fast NT SGEMM (bitwise-frozen ascending-k FMA chain) ---------
__global__ __launch_bounds__(256, 2) void sgemm_nt_fast(const float* __restrict__ A,
                                                        const float* __restrict__ B,
                                                        float* __restrict__ Cmat,
                                                        int N, int K, int ldc)
{
    __shared__ float As[2][16][128];
    __shared__ float Bs[2][16][128];
    const int tid = threadIdx.x;
    const int bm = blockIdx.y * 128;
    const int bn = blockIdx.x * 128;
    const int tx = tid & 15;
    const int ty = tid >> 4;
    const int lr = tid >> 1;
    const int lc = (tid & 1) * 8;

    const float* Ap = A + (size_t)(bm + lr) * K + lc;
    const float* Bp = B + (size_t)(bn + lr) * K + lc;

    float acc[8][8] = {};
    float4 pa0 = *(const float4*)Ap;
    float4 pa1 = *(const float4*)(Ap + 4);
    float4 pb0 = *(const float4*)Bp;
    float4 pb1 = *(const float4*)(Bp + 4);
    int buf = 0;
    As[0][lc + 0][lr] = pa0.x; As[0][lc + 1][lr] = pa0.y;
    As[0][lc + 2][lr] = pa0.z; As[0][lc + 3][lr] = pa0.w;
    As[0][lc + 4][lr] = pa1.x; As[0][lc + 5][lr] = pa1.y;
    As[0][lc + 6][lr] = pa1.z; As[0][lc + 7][lr] = pa1.w;
    Bs[0][lc + 0][lr] = pb0.x; Bs[0][lc + 1][lr] = pb0.y;
    Bs[0][lc + 2][lr] = pb0.z; Bs[0][lc + 3][lr] = pb0.w;
    Bs[0][lc + 4][lr] = pb1.x; Bs[0][lc + 5][lr] = pb1.y;
    Bs[0][lc + 6][lr] = pb1.z; Bs[0][lc + 7][lr] = pb1.w;
    __syncthreads();

    const int ntiles = K >> 4;
    for (int kt = 0; kt < ntiles; kt++) {
        const bool more = (kt + 1 < ntiles);
        if (more) {
            const float* An = Ap + (size_t)(kt + 1) * 16;
            const float* Bn = Bp + (size_t)(kt + 1) * 16;
            pa0 = *(const float4*)An; pa1 = *(const float4*)(An + 4);
            pb0 = *(const float4*)Bn; pb1 = *(const float4*)(Bn + 4);
        }
#pragma unroll
        for (int k = 0; k < 16; k++) {
            float4 a0 = *(const float4*)&As[buf][k][ty * 8];
            float4 a1 = *(const float4*)&As[buf][k][ty * 8 + 4];
            float4 b0 = *(const float4*)&Bs[buf][k][tx * 8];
            float4 b1 = *(const float4*)&Bs[buf][k][tx * 8 + 4];
            float av[8] = {a0.x, a0.y, a0.z, a0.w, a1.x, a1.y, a1.z, a1.w};
            float bv[8] = {b0.x, b0.y, b0.z, b0.w, b1.x, b1.y, b1.z, b1.w};
#pragma unroll
            for (int i = 0; i < 8; i++)
#pragma unroll
                for (int j = 0; j < 8; j++)
                    acc[i][j] = __fmaf_rn(av[i], bv[j], acc[i][j]);
        }
        if (more) {
            buf ^= 1;
            As[buf][lc + 0][lr] = pa0.x; As[buf][lc + 1][lr] = pa0.y;
            As[buf][lc + 2][lr] = pa0.z; As[buf][lc + 3][lr] = pa0.w;
            As[buf][lc + 4][lr] = pa1.x; As[buf][lc + 5][lr] = pa1.y;
            As[buf][lc + 6][lr] = pa1.z; As[buf][lc + 7][lr] = pa1.w;
            Bs[buf][lc + 0][lr] = pb0.x; Bs[buf][lc + 1][lr] = pb0.y;
            Bs[buf][lc + 2][lr] = pb0.z; Bs[buf][lc + 3][lr] = pb0.w;
            Bs[buf][lc + 4][lr] = pb1.x; Bs[buf][lc + 5][lr] = pb1.y;
            Bs[buf][lc + 6][lr] = pb1.z; Bs[buf][lc + 7][lr] = pb1.w;
            __syncthreads();
        }
    }
    (void)N;
#pragma unroll
    for (int i = 0; i < 8; i++) {
        float* Cp = Cmat + (size_t)(bm + ty * 8 + i) * ldc + bn + tx * 8;
        *(float4*)Cp       = make_float4(acc[i][0], acc[i][1], acc[i][2], acc[i][3]);
        *(float4*)(Cp + 4) = make_float4(acc[i][4], acc[i][5], acc[i][6], acc[i][7]);
    }
}

// ================= wmma bf16x3 GEMM (value path; 64x64 tile, 4 warps) ==========
__global__ __launch_bounds__(128) void gemm_wmma_bf16x3(
    const __nv_bfloat16* __restrict__ Ahi, const __nv_bfloat16* __restrict__ Alo,
    const __nv_bfloat16* __restrict__ Bhi, const __nv_bfloat16* __restrict__ Blo,
    float* __restrict__ Cmat, int ldc, int K)
{
    __shared__ __nv_bfloat16 sAhi[64][72];
    __shared__ __nv_bfloat16 sAlo[64][72];
    __shared__ __nv_bfloat16 sBhi[64][72];
    __shared__ __nv_bfloat16 sBlo[64][72];

    const int tid = threadIdx.x;
    const int wid = tid >> 5;
    const int bm = blockIdx.y * 64;
    const int bn = blockIdx.x * 64;
    const int wm = (wid >> 1) * 32;
    const int wn = (wid & 1) * 32;

    wmma::fragment<wmma::accumulator, 16, 16, 16, float> acc[2][2];
#pragma unroll
    for (int i = 0; i < 2; i++)
#pragma unroll
        for (int j = 0; j < 2; j++)
            wmma::fill_fragment(acc[i][j], 0.0f);

    const int nchunks = K >> 6;
    for (int kc = 0; kc < nchunks; kc++) {
        const int kofs = kc * 64;
#pragma unroll
        for (int i = 0; i < 4; i++) {
            int id = tid + i * 128;
            int row = id >> 3, col = (id & 7) * 8;
            *(uint4*)&sAhi[row][col] = *(const uint4*)(Ahi + (size_t)(bm + row) * K + kofs + col);
            *(uint4*)&sAlo[row][col] = *(const uint4*)(Alo + (size_t)(bm + row) * K + kofs + col);
            *(uint4*)&sBhi[row][col] = *(const uint4*)(Bhi + (size_t)(bn + row) * K + kofs + col);
            *(uint4*)&sBlo[row][col] = *(const uint4*)(Blo + (size_t)(bn + row) * K + kofs + col);
        }
        __syncthreads();

#pragma unroll
        for (int kk = 0; kk < 4; kk++) {
            wmma::fragment<wmma::matrix_a, 16, 16, 16, __nv_bfloat16, wmma::row_major> ahi[2], alo[2];
            wmma::fragment<wmma::matrix_b, 16, 16, 16, __nv_bfloat16, wmma::col_major> bhi[2], blo[2];
#pragma unroll
            for (int i = 0; i < 2; i++) {
                wmma::load_matrix_sync(ahi[i], &sAhi[wm + 16 * i][kk * 16], 72);
                wmma::load_matrix_sync(alo[i], &sAlo[wm + 16 * i][kk * 16], 72);
            }
#pragma unroll
            for (int j = 0; j < 2; j++) {
                wmma::load_matrix_sync(bhi[j], &sBhi[wn + 16 * j][kk * 16], 72);
                wmma::load_matrix_sync(blo[j], &sBlo[wn + 16 * j][kk * 16], 72);
            }
#pragma unroll
            for (int i = 0; i < 2; i++)
#pragma unroll
                for (int j = 0; j < 2; j++) {
                    wmma::mma_sync(acc[i][j], ahi[i], bhi[j], acc[i][j]);
                    wmma::mma_sync(acc[i][j], ahi[i], blo[j], acc[i][j]);
                    wmma::mma_sync(acc[i][j], alo[i], bhi[j], acc[i][j]);
                }
        }
        __syncthreads();
    }

#pragma unroll
    for (int i = 0; i < 2; i++)
#pragma unroll
        for (int j = 0; j < 2; j++)
            wmma::store_matrix_sync(Cmat + (size_t)(bm + wm + 16 * i) * ldc + bn + wn + 16 * j,
                                    acc[i][j], ldc, wmma::mem_row_major);
}

// ---------------- RoPE + L2 normalize (bitwise-frozen) -------------------------
__global__ void rope_norm_kernel(const float* __restrict__ qkv,
                                 const float* __restrict__ ct,
                                 const float* __restrict__ st,
                                 float* __restrict__ gq, float* __restrict__ gk)
{
    __shared__ float buf[8][64];
    __shared__ float nrm[8];
    const int w = threadIdx.x >> 5;
    const int gw = (blockIdx.x * blockDim.x + threadIdx.x) >> 5;
    const int lane = threadIdx.x & 31;
    if (gw >= 2 * NH * SLEN) return;
    const int which = (gw >= NH * SLEN) ? 1 : 0;
    const int rem = which ? gw - NH * SLEN : gw;
    const int h = rem >> 11;
    const int s = rem & (SLEN - 1);

    const float* src = qkv + (size_t)s * C3 + which * CDIM + h * HD;
    float x0 = src[2 * lane];
    float x1 = src[2 * lane + 1];

    float cv = ct[s * 32 + lane];
    float sv = st[s * 32 + lane];

    float r0 = __fadd_rn(__fmul_rn(x0, cv), __fmul_rn(-x1, sv));
    float r1 = __fadd_rn(__fmul_rn(x1, cv), __fmul_rn(x0, sv));

    buf[w][2 * lane]     = r0;
    buf[w][2 * lane + 1] = r1;
    __syncwarp();
    if (lane == 0) {
        float l0 = 0.f, l1 = 0.f, l2 = 0.f, l3 = 0.f;
        for (int t = 0; t < 16; t++) {
            float v0 = buf[w][4 * t + 0];
            float v1 = buf[w][4 * t + 1];
            float v2 = buf[w][4 * t + 2];
            float v3 = buf[w][4 * t + 3];
            l0 = __fadd_rn(l0, __fmul_rn(v0, v0));
            l1 = __fadd_rn(l1, __fmul_rn(v1, v1));
            l2 = __fadd_rn(l2, __fmul_rn(v2, v2));
            l3 = __fadd_rn(l3, __fmul_rn(v3, v3));
        }
        float ssum = __fadd_rn(__fadd_rn(l0, l1), __fadd_rn(l2, l3));
        nrm[w] = fmaxf(__fsqrt_rn(ssum), 1e-12f);
    }
    __syncwarp();
    const float nv = nrm[w];

    float* dst = (which ? gk : gq) + ((size_t)h * SLEN + s) * HD;
    dst[2 * lane]     = __fdiv_rn(r0, nv);
    dst[2 * lane + 1] = __fdiv_rn(r1, nv);
}

// ---------------- causal scores (bitwise-frozen chain) -------------------------
__global__ __launch_bounds__(256) void scores_kernel(const float* __restrict__ gq,
                                                     const float* __restrict__ gk,
                                                     float* __restrict__ gs)
{
    const int h = blockIdx.z;
    const int jb = blockIdx.x * 128;
    const int qb = blockIdx.y * 128;
    if (jb > qb) return;

    extern __shared__ float smemf[];
    float (*Qs)[129] = (float(*)[129])smemf;
    float (*Ks)[129] = (float(*)[129])(smemf + 64 * 129);

    const int tid = threadIdx.x;
    const float* qp = gq + ((size_t)h * SLEN + qb) * HD;
    const float* kp = gk + ((size_t)h * SLEN + jb) * HD;
#pragma unroll
    for (int i = 0; i < 32; i++) {
        int idx = tid + i * 256;
        int r = idx >> 6, c = idx & 63;
        Qs[c][r] = qp[idx];
        Ks[c][r] = kp[idx];
    }
    __syncthreads();

    const int tx = tid & 15, ty = tid >> 4;
    float acc[8][8] = {};
#pragma unroll
    for (int k = 0; k < 64; k++) {
        float a[8], b[8];
#pragma unroll
        for (int i = 0; i < 8; i++) a[i] = Qs[k][ty + 16 * i];
#pragma unroll
        for (int j = 0; j < 8; j++) b[j] = Ks[k][tx + 16 * j];
#pragma unroll
        for (int i = 0; i < 8; i++)
#pragma unroll
            for (int j = 0; j < 8; j++)
                acc[i][j] = __fmaf_rn(a[i], b[j], acc[i][j]);
    }
#pragma unroll
    for (int i = 0; i < 8; i++) {
        float* outp = gs + ((size_t)h * SLEN + qb + ty + 16 * i) * SLEN + jb + tx;
#pragma unroll
        for (int j = 0; j < 8; j++)
            outp[16 * j] = __fmul_rn(acc[i][j], 0.125f);
    }
}

// ---------------- helpers ------------------------------------------------------
__device__ __forceinline__ unsigned f2key(float f)
{
    unsigned u = __float_as_uint(f);
    return (u & 0x80000000u) ? ~u : (u | 0x80000000u);
}

// ---------------- hard top-k (two-level radix) + softmax + AV (256 thr) --------
__global__ __launch_bounds__(256) void topk_av_kernel(const float* __restrict__ gs,
                                                      const float* __restrict__ qkv,
                                                      float* __restrict__ ctx)
{
    __shared__ float sc[SLEN];
    __shared__ int   clist[SLEN];
    __shared__ float fred[8];
    __shared__ int   ired[8];
    __shared__ int   hist[256];
    __shared__ int   ss[257];
    __shared__ float s_max;
    __shared__ float s_z;
    __shared__ unsigned s_prefix;
    __shared__ int   s_want;
    __shared__ int   s_cnt;
    __shared__ int   s_tcnt;
    __shared__ int   s_bcnt;
    __shared__ int   tlist[64];
    __shared__ int   sidx[256];
    __shared__ float sw[256];
    __shared__ float yacc[4][64];

    const int row = blockIdx.x;
    const int h = row >> 11;
    const int q = (SLEN - 1) - (row & (SLEN - 1));
    const int n = q + 1;
    const int tid = threadIdx.x;
    const int lane = tid & 31, wid = tid >> 5;
    const bool doSel = (n > TOPK);

    const float* src = gs + ((size_t)h * SLEN + q) * SLEN;

    hist[tid] = 0;
    if (tid == 0) { s_cnt = 0; s_tcnt = 0; s_bcnt = 0; }
    __syncthreads();

    float m = -FLT_MAX;
    const int nIter = (n + 1023) >> 10;
    for (int it = 0; it < nIter; it++) {
        int j0 = it * 1024 + tid * 4;
        float4 v = make_float4(0.f, 0.f, 0.f, 0.f);
        if (j0 + 3 < n) {
            v = *(const float4*)(src + j0);
        } else if (j0 < n) {
            v.x = src[j0];
            if (j0 + 1 < n) v.y = src[j0 + 1];
            if (j0 + 2 < n) v.z = src[j0 + 2];
            if (j0 + 3 < n) v.w = src[j0 + 3];
        }
        if (j0 < n) {
            sc[j0] = v.x;
            if (j0 + 1 < n) sc[j0 + 1] = v.y;
            if (j0 + 2 < n) sc[j0 + 2] = v.z;
            if (j0 + 3 < n) sc[j0 + 3] = v.w;
        }
        float vv[4] = {v.x, v.y, v.z, v.w};
#pragma unroll
        for (int e = 0; e < 4; e++) {
            bool ok = (j0 + e) < n;
            if (ok) m = fmaxf(m, vv[e]);
            if (doSel) {
                int b = ok ? (int)(f2key(vv[e]) >> 24) : -1;
                unsigned same = __match_any_sync(0xffffffffu, b);
                if (b >= 0 && lane == (__ffs(same) - 1)) atomicAdd(&hist[b], __popc(same));
            }
        }
    }
#pragma unroll
    for (int o = 16; o; o >>= 1) m = fmaxf(m, __shfl_xor_sync(0xffffffffu, m, o));
    if (lane == 0) fred[wid] = m;
    __syncthreads();
    if (tid == 0) {
        float mm = fred[0];
        for (int w = 1; w < 8; w++) mm = fmaxf(mm, fred[w]);
        s_max = mm;
    }
    __syncthreads();
    m = s_max;

    const int nPad = (n + 255) & ~255;
    unsigned T = 0;
    int r = 0;

    if (doSel) {
        {
            int v = hist[tid];
#pragma unroll
            for (int off = 1; off < 32; off <<= 1) {
                int o = __shfl_down_sync(0xffffffffu, v, off);
                if (lane + off < 32) v += o;
            }
            if (lane == 0) ired[wid] = v;
            __syncthreads();
            int tail = 0;
            for (int w = wid + 1; w < 8; w++) tail += ired[w];
            int S = v + tail;
            ss[tid] = S;
            if (tid == 255) ss[256] = 0;
            __syncthreads();
            if (S >= TOPK && ss[tid + 1] < TOPK) {
                s_prefix = (unsigned)tid << 24;
                s_want = TOPK - ss[tid + 1];
            }
            __syncthreads();
        }
        unsigned prefix = s_prefix;
        int want = s_want;
        const unsigned btop = prefix >> 24;

        for (int j = tid; j < nPad; j += 256) {
            bool sel = (j < n) && ((f2key(sc[j]) >> 24) == btop);
            unsigned bal = __ballot_sync(0xffffffffu, sel);
            int base = 0;
            if (lane == 0 && bal) base = atomicAdd(&s_bcnt, __popc(bal));
            base = __shfl_sync(0xffffffffu, base, 0);
            if (sel) clist[base + __popc(bal & ((1u << lane) - 1u))] = j;
        }
        __syncthreads();
        const int B = s_bcnt;
        const int BPad = (B + 255) & ~255;

#pragma unroll
        for (int d = 2; d >= 0; d--) {
            hist[tid] = 0;
            __syncthreads();
            const int shift = d * 8;
            const unsigned pmask = 0xFFFFFFFFu << (shift + 8);
            for (int i = tid; i < BPad; i += 256) {
                int b = -1;
                if (i < B) {
                    unsigned k = f2key(sc[clist[i]]);
                    if ((k & pmask) == prefix) b = (int)((k >> shift) & 255u);
                }
                unsigned same = __match_any_sync(0xffffffffu, b);
                if (b >= 0 && lane == (__ffs(same) - 1)) atomicAdd(&hist[b], __popc(same));
            }
            __syncthreads();
            int v = hist[tid];
#pragma unroll
            for (int off = 1; off < 32; off <<= 1) {
                int o = __shfl_down_sync(0xffffffffu, v, off);
                if (lane + off < 32) v += o;
            }
            if (lane == 0) ired[wid] = v;
            __syncthreads();
            int tail = 0;
            for (int w = wid + 1; w < 8; w++) tail += ired[w];
            int S = v + tail;
            ss[tid] = S;
            __syncthreads();
            if (S >= want && ss[tid + 1] < want) {
                s_prefix = prefix | ((unsigned)tid << shift);
                s_want = want - ss[tid + 1];
            }
            __syncthreads();
            prefix = s_prefix;
            want = s_want;
            __syncthreads();
        }
        T = prefix;
        r = want;

        for (int j = tid; j < nPad; j += 256) {
            bool sel = false;
            float f = 0.f;
            unsigned k = 0;
            if (j < n) { f = sc[j]; k = f2key(f); sel = (k > T); }
            unsigned bal = __ballot_sync(0xffffffffu, sel);
            int base = 0;
            if (lane == 0 && bal) base = atomicAdd(&s_cnt, __popc(bal));
            base = __shfl_sync(0xffffffffu, base, 0);
            if (sel) {
                int pos = base + __popc(bal & ((1u << lane) - 1u));
                sidx[pos] = j; sw[pos] = expf(f - m);
            }
            if (j < n && k == T) {
                int p = atomicAdd(&s_tcnt, 1);
                if (p < 64) tlist[p] = j;
            }
        }
        __syncthreads();
        if (tid < s_tcnt && tid < 64) {
            int j = tlist[tid];
            int rank = 0;
            int tc = min(s_tcnt, 64);
            for (int t = 0; t < tc; t++) rank += (tlist[t] < j);
            if (rank < r) {
                int p = atomicAdd(&s_cnt, 1);
                sidx[p] = j; sw[p] = expf(sc[j] - m);
            }
        }
    } else {
        for (int j = tid; j < nPad; j += 256) {
            bool sel = (j < n);
            unsigned bal = __ballot_sync(0xffffffffu, sel);
            int base = 0;
            if (lane == 0 && bal) base = atomicAdd(&s_cnt, __popc(bal));
            base = __shfl_sync(0xffffffffu, base, 0);
            if (sel) {
                int pos = base + __popc(bal & ((1u << lane) - 1u));
                sidx[pos] = j; sw[pos] = expf(sc[j] - m);
            }
        }
    }
    __syncthreads();
    const int ns = min(s_cnt, 256);

    float z = 0.f;
    for (int p = tid; p < ns; p += 256) z += sw[p];
#pragma unroll
    for (int o = 16; o; o >>= 1) z += __shfl_xor_sync(0xffffffffu, z, o);
    if (lane == 0) fred[wid] = z;
    __syncthreads();
    if (tid == 0) {
        float t = 0.f;
        for (int w = 0; w < 8; w++) t += fred[w];
        s_z = t;
    }
    __syncthreads();
    const float Z = s_z;

    const int d = tid & 63, cg2 = tid >> 6;
    const float* vb = qkv + 2 * CDIM + h * HD + d;
    float a0 = 0.f, a1 = 0.f, a2 = 0.f, a3 = 0.f;
    int p = cg2;
    for (; p + 12 < ns; p += 16) {
        a0 = __fmaf_rn(sw[p],      vb[(size_t)sidx[p]      * C3], a0);
        a1 = __fmaf_rn(sw[p + 4],  vb[(size_t)sidx[p + 4]  * C3], a1);
        a2 = __fmaf_rn(sw[p + 8],  vb[(size_t)sidx[p + 8]  * C3], a2);
        a3 = __fmaf_rn(sw[p + 12], vb[(size_t)sidx[p + 12] * C3], a3);
    }
    for (; p < ns; p += 4)
        a0 = __fmaf_rn(sw[p], vb[(size_t)sidx[p] * C3], a0);
    yacc[cg2][d] = (a0 + a1) + (a2 + a3);
    __syncthreads();
    if (tid < 64) {
        float y = (yacc[0][tid] + yacc[1][tid]) + (yacc[2][tid] + yacc[3][tid]);
        ctx[(size_t)q * CDIM + h * HD + tid] = y / Z;
    }
}

// ------------------------------- launcher --------------------------------------
extern "C" void kernel_launch(void* const* d_in, const int* in_sizes, int n_in,
                              void* d_out, int out_size)
{
    (void)in_sizes; (void)n_in; (void)out_size;
    const float* x      = (const float*)d_in[0];
    const float* w_qkv  = (const float*)d_in[1];
    const float* w_proj = (const float*)d_in[2];
    float* out = (float*)d_out;

    float *qkv, *gq, *gk, *gsc, *gctx, *gcos, *gsin;
    __nv_bfloat16 *xhi, *xlo, *wvhi, *wvlo, *wphi, *wplo, *chi, *clo;
    cudaGetSymbolAddress((void**)&qkv,  g_qkv);
    cudaGetSymbolAddress((void**)&gq,   g_q);
    cudaGetSymbolAddress((void**)&gk,   g_k);
    cudaGetSymbolAddress((void**)&gsc,  g_sc);
    cudaGetSymbolAddress((void**)&gctx, g_ctx);
    cudaGetSymbolAddress((void**)&gcos, g_cos);
    cudaGetSymbolAddress((void**)&gsin, g_sin);
    cudaGetSymbolAddress((void**)&xhi,  g_xhi);
    cudaGetSymbolAddress((void**)&xlo,  g_xlo);
    cudaGetSymbolAddress((void**)&wvhi, g_wvhi);
    cudaGetSymbolAddress((void**)&wvlo, g_wvlo);
    cudaGetSymbolAddress((void**)&wphi, g_wphi);
    cudaGetSymbolAddress((void**)&wplo, g_wplo);
    cudaGetSymbolAddress((void**)&chi,  g_chi);
    cudaGetSymbolAddress((void**)&clo,  g_clo);

    static bool init_done = false;
    static cudaStream_t s_aux;
    static cudaEvent_t ev_fork, ev_vdone;
    const int scores_smem = 2 * 64 * 129 * (int)sizeof(float);
    if (!init_done) {
        cudaFuncSetAttribute(scores_kernel,
                             cudaFuncAttributeMaxDynamicSharedMemorySize, scores_smem);
        cudaStreamCreateWithFlags(&s_aux, cudaStreamNonBlocking);
        cudaEventCreateWithFlags(&ev_fork, cudaEventDisableTiming);
        cudaEventCreateWithFlags(&ev_vdone, cudaEventDisableTiming);
        init_done = true;
    }

    // ---- fork: aux stream does splits + v wmma GEMM (independent of qkv chain)
    cudaEventRecord(ev_fork, 0);
    cudaStreamWaitEvent(s_aux, ev_fork, 0);

    split_bf16<<<SLEN * CDIM / 4 / 256, 256, 0, s_aux>>>(x, xhi, xlo, SLEN * CDIM);
    split_bf16<<<CDIM * CDIM / 4 / 256, 256, 0, s_aux>>>(w_qkv + 2 * CDIM * CDIM,
                                                         wvhi, wvlo, CDIM * CDIM);
    split_bf16<<<CDIM * CDIM / 4 / 256, 256, 0, s_aux>>>(w_proj, wphi, wplo, CDIM * CDIM);
    // v = x @ w_qkv[2048:3072]^T  (wmma bf16x3) — writes qkv cols [2048,3072)
    gemm_wmma_bf16x3<<<dim3(CDIM / 64, SLEN / 64), 128, 0, s_aux>>>(
        xhi, xlo, wvhi, wvlo, qkv + 2 * CDIM, C3, CDIM);
    cudaEventRecord(ev_vdone, s_aux);

    // ---- main chain: tables, q/k GEMM (cols [0,2048)), rope, scores ----
    build_tables<<<(SLEN * 32 + 255) / 256, 256>>>(gcos, gsin);
    sgemm_nt_fast<<<dim3(2048 / 128, SLEN / 128), 256>>>(x, w_qkv, qkv, 2048, CDIM, C3);
    {
        int warps = 2 * NH * SLEN;
        int blocks = (warps * 32 + 255) / 256;
        rope_norm_kernel<<<blocks, 256>>>(qkv, gcos, gsin, gq, gk);
    }
    scores_kernel<<<dim3(SLEN / 128, SLEN / 128, NH), 256, scores_smem>>>(gq, gk, gsc);

    // ---- join: topk needs v (aux) + scores (main) ----
    cudaStreamWaitEvent(0, ev_vdone, 0);
    topk_av_kernel<<<NH * SLEN, 256>>>(gsc, qkv, gctx);

    // ---- projection ----
    split_bf16<<<SLEN * CDIM / 4 / 256, 256>>>(gctx, chi, clo, SLEN * CDIM);
    gemm_wmma_bf16x3<<<dim3(CDIM / 64, SLEN / 64), 128>>>(
        chi, clo, wphi, wplo, out, CDIM, CDIM);
}